// round 15
// baseline (speedup 1.0000x reference)
#include <cuda_runtime.h>
#include <cuda_bf16.h>
#include <cstdint>

// Problem constants: B*C = 16, L = 128, N = 48
#define BC 16

// Scratch (device globals; allocation in kernel_launch is forbidden)
__device__ float g_bufA[(size_t)BC * 16384 * 48];   // S1 out [bc][p][h][w]; later dec2 out [bc][r][d][h]
__device__ float g_bufC[(size_t)BC * 48 * 48 * 48]; // enc [bc][r][p][q]

// Precomputed W fragments (mma.m16n8k16 B-operand layout), bf16 hi/lo split.
__device__ uint2 g_wfHi[6][1536];
__device__ uint2 g_wfLo[6][1536];

__device__ __forceinline__ float bf16hi(float v) {
    return __bfloat162float(__float2bfloat16_rn(v));
}
__device__ __forceinline__ uint32_t packbf2(float a, float b) {
    __nv_bfloat162 t = __floats2bfloat162_rn(a, b);
    return *reinterpret_cast<uint32_t*>(&t);
}

__device__ __forceinline__ void mma_bf16(float d[4], const uint4& a, const uint2& b) {
    asm volatile(
        "mma.sync.aligned.m16n8k16.row.col.f32.bf16.bf16.f32 "
        "{%0,%1,%2,%3}, {%4,%5,%6,%7}, {%8,%9}, {%0,%1,%2,%3};"
        : "+f"(d[0]), "+f"(d[1]), "+f"(d[2]), "+f"(d[3])
        : "r"(a.x), "r"(a.y), "r"(a.z), "r"(a.w), "r"(b.x), "r"(b.y));
}

__device__ __forceinline__ uint4 ldsm_t(uint32_t addr) {
    uint4 r;
    asm volatile(
        "ldmatrix.sync.aligned.m8n8.x4.trans.shared.b16 {%0,%1,%2,%3}, [%4];"
        : "=r"(r.x), "=r"(r.y), "=r"(r.z), "=r"(r.w) : "r"(addr));
    return r;
}

// Build m16n8k16 B-fragment layout for all 6 weight matrices (bf16 hi/lo split).
__global__ void prep_wfrag(const float* __restrict__ W0, const float* __restrict__ W1,
                           const float* __restrict__ W2, const float* __restrict__ W3,
                           const float* __restrict__ W4, const float* __restrict__ W5)
{
    const int m = blockIdx.y;
    const float* W = (m==0)?W0:(m==1)?W1:(m==2)?W2:(m==3)?W3:(m==4)?W4:W5;
    const int M   = (m < 3) ? 48 : 128;
    const int NMT = M / 8;
    const int t = blockIdx.x * blockDim.x + threadIdx.x;   // 0..1535
    const int rem  = t % (NMT * 32);
    const int kc   = t / (NMT * 32);
    const int mt   = rem / 32;
    const int lane = rem % 32;
    const int tq = lane & 3, gid = lane >> 2;
    const int k0 = kc * 16 + 2 * tq;
    const int c  = mt * 8 + gid;
    const float w00 = W[(k0    ) * M + c], w01 = W[(k0 + 1) * M + c];
    const float w08 = W[(k0 + 8) * M + c], w09 = W[(k0 + 9) * M + c];
    const float h00 = bf16hi(w00), h01 = bf16hi(w01);
    const float h08 = bf16hi(w08), h09 = bf16hi(w09);
    g_wfHi[m][t] = make_uint2(packbf2(h00, h01), packbf2(h08, h09));
    g_wfLo[m][t] = make_uint2(packbf2(w00 - h00, w01 - h01), packbf2(w08 - h08, w09 - h09));
}

// ---- generic mma accumulation over smem bf16 hi/lo panels [k][j], pad PJ ----
// warp = mt0-group (warp%MWARPS) x j-group (warp/MWARPS, NSL strips each).
template<int K, int M, int MWARPS, int NTILE, int NSL, int PJ>
__device__ __forceinline__ void gemm_acc(
    const __nv_bfloat16* AsH, const __nv_bfloat16* AsL,
    const uint2* __restrict__ wHi, const uint2* __restrict__ wLo,
    int warp, int lane, float acc[NSL][NTILE][4])
{
    constexpr int KC  = K / 16;
    constexpr int NMT = M / 8;
    const int mt0 = (warp % MWARPS) * NTILE;
    const int s0  = (warp / MWARPS) * NSL;
    const uint32_t aH0 = (uint32_t)__cvta_generic_to_shared(AsH);
    const uint32_t aL0 = (uint32_t)__cvta_generic_to_shared(AsL);
    const uint32_t lrow = ((lane & 16) >> 1) + (lane & 7);
    const uint32_t lcol = (lane & 8);
    const uint32_t lofs = 2 * (lrow * PJ + lcol);

#pragma unroll
    for (int sl = 0; sl < NSL; sl++)
#pragma unroll
        for (int nt = 0; nt < NTILE; nt++)
#pragma unroll
            for (int r = 0; r < 4; r++) acc[sl][nt][r] = 0.0f;

    uint2 bh[2][NTILE], bl[2][NTILE];
#pragma unroll
    for (int nt = 0; nt < NTILE; nt++) {
        bh[0][nt] = __ldg(&wHi[(mt0 + nt) * 32 + lane]);
        bl[0][nt] = __ldg(&wLo[(mt0 + nt) * 32 + lane]);
    }

#pragma unroll
    for (int kc = 0; kc < KC; kc++) {
        const int cur = kc & 1, nxt = cur ^ 1;
        if (kc + 1 < KC) {
#pragma unroll
            for (int nt = 0; nt < NTILE; nt++) {
                bh[nxt][nt] = __ldg(&wHi[((kc + 1) * NMT + mt0 + nt) * 32 + lane]);
                bl[nxt][nt] = __ldg(&wLo[((kc + 1) * NMT + mt0 + nt) * 32 + lane]);
            }
        }
#pragma unroll
        for (int sl = 0; sl < NSL; sl++) {
            const uint32_t toff = 2 * (kc * 16 * PJ + (s0 + sl) * 16) + lofs;
            const uint4 ah = ldsm_t(aH0 + toff);
            const uint4 al = ldsm_t(aL0 + toff);
#pragma unroll
            for (int nt = 0; nt < NTILE; nt++) {
                mma_bf16(acc[sl][nt], al, bh[cur][nt]);   // small terms first
                mma_bf16(acc[sl][nt], ah, bl[cur][nt]);
                mma_bf16(acc[sl][nt], ah, bh[cur][nt]);
            }
        }
    }
}

// ---- epilogue: acc -> smem bf16 hi/lo panel [j][m], pad PM ----
template<int MWARPS, int NTILE, int NSL, int PM>
__device__ __forceinline__ void epi_smem(
    const float acc[NSL][NTILE][4], __nv_bfloat16* TH, __nv_bfloat16* TL,
    int warp, int lane)
{
    const int mt0 = (warp % MWARPS) * NTILE;
    const int s0  = (warp / MWARPS) * NSL;
    const int tq = lane & 3, gid = lane >> 2;
#pragma unroll
    for (int sl = 0; sl < NSL; sl++) {
        const int j = (s0 + sl) * 16 + gid;
#pragma unroll
        for (int nt = 0; nt < NTILE; nt++) {
            const int mc = (mt0 + nt) * 8 + 2 * tq;
            const float v0 = acc[sl][nt][0], v1 = acc[sl][nt][1];
            const float v2 = acc[sl][nt][2], v3 = acc[sl][nt][3];
            const float h0 = bf16hi(v0), h1 = bf16hi(v1);
            const float h2 = bf16hi(v2), h3 = bf16hi(v3);
            *reinterpret_cast<uint32_t*>(&TH[j * PM + mc])       = packbf2(h0, h1);
            *reinterpret_cast<uint32_t*>(&TL[j * PM + mc])       = packbf2(v0 - h0, v1 - h1);
            *reinterpret_cast<uint32_t*>(&TH[(j + 8) * PM + mc]) = packbf2(h2, h3);
            *reinterpret_cast<uint32_t*>(&TL[(j + 8) * PM + mc]) = packbf2(v2 - h2, v3 - h3);
        }
    }
}

// ---- staging: global fp32 [k][j] (row stride J) -> smem bf16 hi/lo [k][j] pad PJ ----
template<int K, int BJ, int PJ, int NT>
__device__ __forceinline__ void stage_panel(
    const float* __restrict__ src, int J,
    __nv_bfloat16* AsH, __nv_bfloat16* AsL, int tid)
{
#pragma unroll
    for (int idx = tid; idx < K * BJ / 4; idx += NT) {
        const int k  = idx / (BJ / 4);
        const int jq = (idx % (BJ / 4)) * 4;
        const float4 v = *reinterpret_cast<const float4*>(&src[(size_t)k * J + jq]);
        const float h0 = bf16hi(v.x), h1 = bf16hi(v.y), h2 = bf16hi(v.z), h3 = bf16hi(v.w);
        *reinterpret_cast<uint2*>(&AsH[k * PJ + jq]) =
            make_uint2(packbf2(h0, h1), packbf2(h2, h3));
        *reinterpret_cast<uint2*>(&AsL[k * PJ + jq]) =
            make_uint2(packbf2(v.x - h0, v.y - h1), packbf2(v.z - h2, v.w - h3));
    }
}

// ---- S1 / S6: single contraction, out[b][j][m] (or transposed out[b][m][j]) ----
template<int K, int M, int NW, int NS, int MWARPS, int NTILE, int MINB, bool TRANSOUT>
__global__ void __launch_bounds__(NW * 32, MINB) mma_stage(
    const float* __restrict__ in, const uint2* __restrict__ wHi,
    const uint2* __restrict__ wLo, float* __restrict__ out, int J)
{
    constexpr int BJ  = NS * 16;
    constexpr int PJ  = BJ + 8;
    constexpr int JW  = NW / MWARPS;
    constexpr int NSL = NS / JW;
    constexpr int NT  = NW * 32;

    __shared__ __nv_bfloat16 AsH[K * PJ];
    __shared__ __nv_bfloat16 AsL[K * PJ];

    const int tid  = threadIdx.x;
    const int lane = tid & 31, warp = tid >> 5;
    const int tq = lane & 3, gid = lane >> 2;
    const int b  = blockIdx.z;
    const int j0 = blockIdx.x * BJ;
    const int mt0 = (warp % MWARPS) * NTILE;
    const int s0  = (warp / MWARPS) * NSL;

    stage_panel<K, BJ, PJ, NT>(in + (size_t)b * K * J + j0, J, AsH, AsL, tid);
    __syncthreads();

    float acc[NSL][NTILE][4];
    gemm_acc<K, M, MWARPS, NTILE, NSL, PJ>(AsH, AsL, wHi, wLo, warp, lane, acc);

#pragma unroll
    for (int sl = 0; sl < NSL; sl++) {
        const int j = j0 + (s0 + sl) * 16 + gid;
#pragma unroll
        for (int nt = 0; nt < NTILE; nt++) {
            const int mc = (mt0 + nt) * 8 + 2 * tq;
            if (TRANSOUT) {
                float* op = out + (size_t)b * J * M;
                op[(size_t)(mc)     * J + j]     = acc[sl][nt][0];
                op[(size_t)(mc + 1) * J + j]     = acc[sl][nt][1];
                op[(size_t)(mc)     * J + j + 8] = acc[sl][nt][2];
                op[(size_t)(mc + 1) * J + j + 8] = acc[sl][nt][3];
            } else {
                float* op = out + (size_t)b * J * M + (size_t)j * M;
                *reinterpret_cast<float2*>(&op[mc]) =
                    make_float2(acc[sl][nt][0], acc[sl][nt][1]);
                *reinterpret_cast<float2*>(&op[(size_t)8 * M + mc]) =
                    make_float2(acc[sl][nt][2], acc[sl][nt][3]);
            }
        }
    }
}

// ---- enc2: fused S2+S3. Block (p=blockIdx.x, bc=blockIdx.z). ----
// in [bc][p][h][w] slab (128x128) -> T1[w][q] -> enc[bc][r][p][q]
__global__ void __launch_bounds__(256, 1) enc2_kernel(
    const float* __restrict__ in, const uint2* __restrict__ wH2,
    const uint2* __restrict__ wL2, const uint2* __restrict__ wH1,
    const uint2* __restrict__ wL1, float* __restrict__ enc)
{
    extern __shared__ __align__(16) char sm[];
    __nv_bfloat16* slabH = reinterpret_cast<__nv_bfloat16*>(sm);
    __nv_bfloat16* slabL = slabH + 128 * 136;
    __nv_bfloat16* T1H   = slabL + 128 * 136;
    __nv_bfloat16* T1L   = T1H + 128 * 56;

    const int tid = threadIdx.x, lane = tid & 31, warp = tid >> 5;
    const int tq = lane & 3, gid = lane >> 2;
    const int p = blockIdx.x, bc = blockIdx.z;

    // stage slab [h=128][w=128]
    stage_panel<128, 128, 136, 256>(in + ((size_t)bc * 48 + p) * 16384, 128,
                                    slabH, slabL, tid);
    __syncthreads();

    // GEMM1: contract h. K=128, J=128(w), M=48(q). 8 warps: MWARPS=2, NTILE=3, NSL=2.
    {
        float acc[2][3][4];
        gemm_acc<128, 48, 2, 3, 2, 136>(slabH, slabL, wH2, wL2, warp, lane, acc);
        epi_smem<2, 3, 2, 56>(acc, T1H, T1L, warp, lane);
    }
    __syncthreads();

    // GEMM2: contract w. K=128, J=48(q), M=48(r). 6 active warps: MWARPS=2, NTILE=3, NSL=1.
    if (warp < 6) {
        float acc[1][3][4];
        gemm_acc<128, 48, 2, 3, 1, 56>(T1H, T1L, wH1, wL1, warp, lane, acc);
        const int mt0 = (warp % 2) * 3;
        const int s0  = (warp / 2);
        const int q = s0 * 16 + gid;
        float* ob = enc + (size_t)bc * 110592 + p * 48;   // [bc][r][p][q]
#pragma unroll
        for (int nt = 0; nt < 3; nt++) {
            const int r = (mt0 + nt) * 8 + 2 * tq;
            ob[(size_t)(r)     * 2304 + q]     = acc[0][nt][0];
            ob[(size_t)(r + 1) * 2304 + q]     = acc[0][nt][1];
            ob[(size_t)(r)     * 2304 + q + 8] = acc[0][nt][2];
            ob[(size_t)(r + 1) * 2304 + q + 8] = acc[0][nt][3];
        }
    }
}

// ---- dec2: fused S4+S5. Block (r=blockIdx.x, bc=blockIdx.z). ----
// enc[bc][r][p][q] slab (48x48) -> T[q][d] -> out [bc][r][d][h]
__global__ void __launch_bounds__(256, 2) dec2_kernel(
    const float* __restrict__ enc, const uint2* __restrict__ wH3,
    const uint2* __restrict__ wL3, const uint2* __restrict__ wH4,
    const uint2* __restrict__ wL4, float* __restrict__ out)
{
    __shared__ __nv_bfloat16 slabH[48 * 56];
    __shared__ __nv_bfloat16 slabL[48 * 56];
    __shared__ __nv_bfloat16 TH[48 * 136];
    __shared__ __nv_bfloat16 TL[48 * 136];

    const int tid = threadIdx.x, lane = tid & 31, warp = tid >> 5;
    const int tq = lane & 3, gid = lane >> 2;
    const int r = blockIdx.x, bc = blockIdx.z;

    // stage slab [p=48][q=48]
    stage_panel<48, 48, 56, 256>(enc + (size_t)bc * 110592 + (size_t)r * 2304, 48,
                                 slabH, slabL, tid);
    __syncthreads();

    // GEMM1: contract p. K=48, J=48(q), M=128(d). 8 warps: MWARPS=8, NTILE=2, NSL=3.
    {
        float acc[3][2][4];
        gemm_acc<48, 128, 8, 2, 3, 56>(slabH, slabL, wH3, wL3, warp, lane, acc);
        epi_smem<8, 2, 3, 136>(acc, TH, TL, warp, lane);
    }
    __syncthreads();

    // GEMM2: contract q. K=48, J=128(d), M=128(h). 8 warps: MWARPS=4, NTILE=4, NSL=4.
    {
        float acc[4][4][4];
        gemm_acc<48, 128, 4, 4, 4, 136>(TH, TL, wH4, wL4, warp, lane, acc);
        const int mt0 = (warp % 4) * 4;
        const int s0  = (warp / 4) * 4;
        float* ob = out + ((size_t)bc * 48 + r) * 16384;   // [d][h]
#pragma unroll
        for (int sl = 0; sl < 4; sl++) {
            const int d = (s0 + sl) * 16 + gid;
#pragma unroll
            for (int nt = 0; nt < 4; nt++) {
                const int mc = (mt0 + nt) * 8 + 2 * tq;
                *reinterpret_cast<float2*>(&ob[(size_t)d * 128 + mc]) =
                    make_float2(acc[sl][nt][0], acc[sl][nt][1]);
                *reinterpret_cast<float2*>(&ob[(size_t)(d + 8) * 128 + mc]) =
                    make_float2(acc[sl][nt][2], acc[sl][nt][3]);
            }
        }
    }
}

extern "C" void kernel_launch(void* const* d_in, const int* in_sizes, int n_in,
                              void* d_out, int out_size)
{
    const float* x   = (const float*)d_in[0];
    const float* EN3 = (const float*)d_in[1];
    const float* EN2 = (const float*)d_in[2];
    const float* EN1 = (const float*)d_in[3];
    const float* DE3 = (const float*)d_in[4];
    const float* DE2 = (const float*)d_in[5];
    const float* DE1 = (const float*)d_in[6];
    float* out = (float*)d_out;

    float *bufA, *bufC;
    cudaGetSymbolAddress((void**)&bufA, g_bufA);
    cudaGetSymbolAddress((void**)&bufC, g_bufC);
    uint2 *wfHi, *wfLo;
    cudaGetSymbolAddress((void**)&wfHi, g_wfHi);
    cudaGetSymbolAddress((void**)&wfLo, g_wfLo);

    prep_wfrag<<<dim3(12, 6), 128>>>(EN3, EN2, EN1, DE3, DE2, DE1);

    constexpr int ENC2_SMEM = (128 * 136 + 128 * 56) * 2 * 2;   // 98304 B
    static bool attr_set = false;
    cudaFuncSetAttribute(enc2_kernel, cudaFuncAttributeMaxDynamicSharedMemorySize, ENC2_SMEM);
    (void)attr_set;

    // (single decode ordering == averaged result exactly; mode contractions commute)
    auto s1 = mma_stage<128, 48, 4, 4, 2, 3, 6, true>;    // contract d -> [bc][p][h][w]
    auto s6 = mma_stage<48, 128, 8, 4, 8, 2, 3, false>;   // contract r -> [bc][d][h][w]

    // S1: x[bc][d][hw] (J=16384) -> bufA = [bc][p][h][w]
    s1<<<dim3(256, 1, BC), 128>>>(x, wfHi + 0*1536, wfLo + 0*1536, bufA, 16384);
    // enc2: fused S2+S3 -> bufC = enc [bc][r][p][q]
    enc2_kernel<<<dim3(48, 1, BC), 256, ENC2_SMEM>>>(
        bufA, wfHi + 1*1536, wfLo + 1*1536, wfHi + 2*1536, wfLo + 2*1536, bufC);
    // dec2: fused S4+S5 -> bufA = [bc][r][d][h]
    dec2_kernel<<<dim3(48, 1, BC), 256>>>(
        bufC, wfHi + 3*1536, wfLo + 3*1536, wfHi + 4*1536, wfLo + 4*1536, bufA);
    // S6: contract r. bufA[bc][r][dh] (J=16384) -> out = [b][c][d][h][w]
    s6<<<dim3(256, 1, BC), 256>>>(bufA, wfHi + 5*1536, wfLo + 5*1536, out, 16384);
}

// round 16
// speedup vs baseline: 1.0167x; 1.0167x over previous
#include <cuda_runtime.h>
#include <cuda_bf16.h>
#include <cstdint>

// Problem constants: B*C = 16, L = 128, N = 48
#define BC 16

// Scratch (device globals; allocation in kernel_launch is forbidden)
__device__ float g_bufA[(size_t)BC * 16384 * 48];
__device__ float g_bufB[(size_t)BC * 6144  * 48];
__device__ float g_bufC[(size_t)BC * 2304  * 48];

// Precomputed W fragments (mma.m16n8k16 B-operand layout), bf16 hi/lo split.
__device__ uint2 g_wfHi[6][1536];
__device__ uint2 g_wfLo[6][1536];

__device__ __forceinline__ float bf16hi(float v) {
    return __bfloat162float(__float2bfloat16_rn(v));
}
__device__ __forceinline__ uint32_t packbf2(float a, float b) {
    __nv_bfloat162 t = __floats2bfloat162_rn(a, b);
    return *reinterpret_cast<uint32_t*>(&t);
}

__device__ __forceinline__ void mma_bf16(float d[4], const uint4& a, const uint2& b) {
    asm volatile(
        "mma.sync.aligned.m16n8k16.row.col.f32.bf16.bf16.f32 "
        "{%0,%1,%2,%3}, {%4,%5,%6,%7}, {%8,%9}, {%0,%1,%2,%3};"
        : "+f"(d[0]), "+f"(d[1]), "+f"(d[2]), "+f"(d[3])
        : "r"(a.x), "r"(a.y), "r"(a.z), "r"(a.w), "r"(b.x), "r"(b.y));
}

// ldmatrix x4 transposed: builds m16n8k16 A-fragment from [k][j] bf16 smem.
__device__ __forceinline__ uint4 ldsm_t(uint32_t addr) {
    uint4 r;
    asm volatile(
        "ldmatrix.sync.aligned.m8n8.x4.trans.shared.b16 {%0,%1,%2,%3}, [%4];"
        : "=r"(r.x), "=r"(r.y), "=r"(r.z), "=r"(r.w) : "r"(addr));
    return r;
}

// Build m16n8k16 B-fragment layout for all 6 weight matrices (bf16 hi/lo split).
__global__ void prep_wfrag(const float* __restrict__ W0, const float* __restrict__ W1,
                           const float* __restrict__ W2, const float* __restrict__ W3,
                           const float* __restrict__ W4, const float* __restrict__ W5)
{
    const int m = blockIdx.y;
    const float* W = (m==0)?W0:(m==1)?W1:(m==2)?W2:(m==3)?W3:(m==4)?W4:W5;
    const int M   = (m < 3) ? 48 : 128;
    const int NMT = M / 8;
    const int t = blockIdx.x * blockDim.x + threadIdx.x;   // 0..1535
    const int rem  = t % (NMT * 32);
    const int kc   = t / (NMT * 32);
    const int mt   = rem / 32;
    const int lane = rem % 32;
    const int tq = lane & 3, gid = lane >> 2;
    const int k0 = kc * 16 + 2 * tq;
    const int c  = mt * 8 + gid;
    const float w00 = W[(k0    ) * M + c], w01 = W[(k0 + 1) * M + c];
    const float w08 = W[(k0 + 8) * M + c], w09 = W[(k0 + 9) * M + c];
    const float h00 = bf16hi(w00), h01 = bf16hi(w01);
    const float h08 = bf16hi(w08), h09 = bf16hi(w09);
    g_wfHi[m][t] = make_uint2(packbf2(h00, h01), packbf2(h08, h09));
    g_wfLo[m][t] = make_uint2(packbf2(w00 - h00, w01 - h01), packbf2(w08 - h08, w09 - h09));
}

// out[b][j][m] = sum_k in[b][k][j] * W[k][m]   (bf16 2-split, 3 products, m16n8k16)
// MWARPS m-warps x JW j-groups; each warp: NSL strips x NTILE 8-wide m-tiles.
// A panel staged COALESCED (LDG.128) into [k][j] bf16 hi/lo DYNAMIC smem (PJ pad);
// fragments built by ldmatrix.x4.trans at use. B fragments double-buffered in regs.
template<int K, int M, int NW, int NS, int MWARPS, int NTILE, int MINB>
__global__ void __launch_bounds__(NW * 32, MINB) mma_stage(
    const float* __restrict__ in, const uint2* __restrict__ wHi,
    const uint2* __restrict__ wLo, float* __restrict__ out, int J)
{
    constexpr int KC  = K / 16;
    constexpr int NMT = M / 8;
    constexpr int BJ  = NS * 16;
    constexpr int PJ  = BJ + 8;            // bf16 pad: conflict-spread rows
    constexpr int JW  = NW / MWARPS;
    constexpr int NSL = NS / JW;
    constexpr int NT  = NW * 32;

    extern __shared__ __nv_bfloat16 smbuf[];
    __nv_bfloat16* AsH = smbuf;
    __nv_bfloat16* AsL = smbuf + K * PJ;

    const int tid  = threadIdx.x;
    const int lane = tid & 31, warp = tid >> 5;
    const int tq = lane & 3, gid = lane >> 2;
    const int b  = blockIdx.z;
    const int j0 = blockIdx.x * BJ;
    const int mt0 = (warp % MWARPS) * NTILE;
    const int s0  = (warp / MWARPS) * NSL;

    // ---- preload first B fragments (overlaps staging) ----
    uint2 bh[2][NTILE], bl[2][NTILE];
#pragma unroll
    for (int nt = 0; nt < NTILE; nt++) {
        bh[0][nt] = __ldg(&wHi[(mt0 + nt) * 32 + lane]);
        bl[0][nt] = __ldg(&wLo[(mt0 + nt) * 32 + lane]);
    }

    // ---- stage A panel: coalesced float4 loads, hi/lo bf16 split, STS.64 ----
    const float* inb = in + (size_t)b * K * J + j0;
#pragma unroll
    for (int idx = tid; idx < K * BJ / 4; idx += NT) {
        const int k  = idx / (BJ / 4);
        const int jq = (idx % (BJ / 4)) * 4;
        const float4 v = *reinterpret_cast<const float4*>(&inb[(size_t)k * J + jq]);
        const float h0 = bf16hi(v.x), h1 = bf16hi(v.y), h2 = bf16hi(v.z), h3 = bf16hi(v.w);
        *reinterpret_cast<uint2*>(&AsH[k * PJ + jq]) =
            make_uint2(packbf2(h0, h1), packbf2(h2, h3));
        *reinterpret_cast<uint2*>(&AsL[k * PJ + jq]) =
            make_uint2(packbf2(v.x - h0, v.y - h1), packbf2(v.z - h2, v.w - h3));
    }
    __syncthreads();

    // per-lane ldmatrix base offset (bytes) within a (kc, s) tile
    const uint32_t aH0 = (uint32_t)__cvta_generic_to_shared(AsH);
    const uint32_t aL0 = (uint32_t)__cvta_generic_to_shared(AsL);
    const uint32_t lrow = ((lane & 16) >> 1) + (lane & 7);   // k row within tile
    const uint32_t lcol = (lane & 8);                        // j col within tile
    const uint32_t lofs = 2 * (lrow * PJ + lcol);

    float acc[NSL][NTILE][4];
#pragma unroll
    for (int sl = 0; sl < NSL; sl++)
#pragma unroll
        for (int nt = 0; nt < NTILE; nt++)
#pragma unroll
            for (int r = 0; r < 4; r++) acc[sl][nt][r] = 0.0f;

#pragma unroll
    for (int kc = 0; kc < KC; kc++) {
        const int cur = kc & 1, nxt = cur ^ 1;
        if (kc + 1 < KC) {
#pragma unroll
            for (int nt = 0; nt < NTILE; nt++) {
                bh[nxt][nt] = __ldg(&wHi[((kc + 1) * NMT + mt0 + nt) * 32 + lane]);
                bl[nxt][nt] = __ldg(&wLo[((kc + 1) * NMT + mt0 + nt) * 32 + lane]);
            }
        }
#pragma unroll
        for (int sl = 0; sl < NSL; sl++) {
            const uint32_t toff = 2 * (kc * 16 * PJ + (s0 + sl) * 16) + lofs;
            const uint4 ah = ldsm_t(aH0 + toff);
            const uint4 al = ldsm_t(aL0 + toff);
#pragma unroll
            for (int nt = 0; nt < NTILE; nt++) {
                mma_bf16(acc[sl][nt], al, bh[cur][nt]);   // small terms first
                mma_bf16(acc[sl][nt], ah, bl[cur][nt]);
                mma_bf16(acc[sl][nt], ah, bh[cur][nt]);
            }
        }
    }

    // ---- write out ----
#pragma unroll
    for (int sl = 0; sl < NSL; sl++) {
        float* op = out + (size_t)b * J * M + (size_t)(j0 + (s0 + sl) * 16 + gid) * M;
#pragma unroll
        for (int nt = 0; nt < NTILE; nt++) {
            const int mc = (mt0 + nt) * 8 + 2 * tq;
            *reinterpret_cast<float2*>(&op[mc]) =
                make_float2(acc[sl][nt][0], acc[sl][nt][1]);
            *reinterpret_cast<float2*>(&op[(size_t)8 * M + mc]) =
                make_float2(acc[sl][nt][2], acc[sl][nt][3]);
        }
    }
}

extern "C" void kernel_launch(void* const* d_in, const int* in_sizes, int n_in,
                              void* d_out, int out_size)
{
    const float* x   = (const float*)d_in[0];
    const float* EN3 = (const float*)d_in[1];
    const float* EN2 = (const float*)d_in[2];
    const float* EN1 = (const float*)d_in[3];
    const float* DE3 = (const float*)d_in[4];
    const float* DE2 = (const float*)d_in[5];
    const float* DE1 = (const float*)d_in[6];
    float* out = (float*)d_out;

    float *bufA, *bufB, *bufC;
    cudaGetSymbolAddress((void**)&bufA, g_bufA);
    cudaGetSymbolAddress((void**)&bufB, g_bufB);
    cudaGetSymbolAddress((void**)&bufC, g_bufC);
    uint2 *wfHi, *wfLo;
    cudaGetSymbolAddress((void**)&wfHi, g_wfHi);
    cudaGetSymbolAddress((void**)&wfLo, g_wfLo);

    prep_wfrag<<<dim3(12, 6), 128>>>(EN3, EN2, EN1, DE3, DE2, DE1);

    // Stage-shaped tiling:
    //  S1 (big DRAM reader):  enc BJ=128, NW=8 (MWARPS=2, NTILE=3, JW=4, NSL=2), 69.6KB dyn smem, 3/SM.
    //  S2:                    enc BJ=64, NW=4 (NSL=2)  [round-13 winner]
    //  S3 (tiny, L2-res):     enc BJ=32, NW=4 (NSL=1)  -> grid 1152
    //  S4 (tiny, L2-res):     dec BJ=32, NW=8 (NSL=2)  -> grid 1152
    //  S5:                    dec BJ=64, NW=8 (NSL=4)  [round-13 winner]
    //  S6 (big DRAM writer):  dec BJ=64, NW=8 (NSL=4)  [round-13 winner]
    // (single decode ordering == averaged result exactly; mode contractions commute)
    auto encF = mma_stage<128, 48, 8, 8, 2, 3, 3>;   // BJ=128
    auto enc64 = mma_stage<128, 48, 4, 4, 2, 3, 6>;  // BJ=64
    auto enc32 = mma_stage<128, 48, 4, 2, 2, 3, 8>;  // BJ=32
    auto dec32 = mma_stage<48, 128, 8, 2, 8, 2, 4>;  // BJ=32
    auto dec64 = mma_stage<48, 128, 8, 4, 8, 2, 3>;  // BJ=64

    constexpr int SM_ENCF  = 128 * 136 * 2 * 2;   // 69632
    constexpr int SM_ENC64 = 128 * 72  * 2 * 2;   // 36864
    constexpr int SM_ENC32 = 128 * 40  * 2 * 2;   // 20480
    constexpr int SM_DEC32 = 48  * 40  * 2 * 2;   // 7680
    constexpr int SM_DEC64 = 48  * 72  * 2 * 2;   // 13824
    cudaFuncSetAttribute(encF,  cudaFuncAttributeMaxDynamicSharedMemorySize, SM_ENCF);
    cudaFuncSetAttribute(enc64, cudaFuncAttributeMaxDynamicSharedMemorySize, SM_ENC64);
    cudaFuncSetAttribute(enc32, cudaFuncAttributeMaxDynamicSharedMemorySize, SM_ENC32);
    cudaFuncSetAttribute(dec32, cudaFuncAttributeMaxDynamicSharedMemorySize, SM_DEC32);
    cudaFuncSetAttribute(dec64, cudaFuncAttributeMaxDynamicSharedMemorySize, SM_DEC64);

    // S1: contract d.  x[bc][d][hw]   (J=16384) -> bufA = [bc][h][w][p]
    encF<<<dim3(128, 1, BC), 256, SM_ENCF>>>(x, wfHi + 0*1536, wfLo + 0*1536, bufA, 16384);
    // S2: contract h.  bufA[bc][h][wp] (J=6144) -> bufB = [bc][w][p][q]
    enc64<<<dim3(96, 1, BC), 128, SM_ENC64>>>(bufA, wfHi + 1*1536, wfLo + 1*1536, bufB, 6144);
    // S3: contract w.  bufB[bc][w][pq] (J=2304) -> bufC = enc = [bc][p][q][r]
    enc32<<<dim3(72, 1, BC), 128, SM_ENC32>>>(bufB, wfHi + 2*1536, wfLo + 2*1536, bufC, 2304);

    // S4: contract p.  enc[bc][p][qr]  (J=2304) -> bufB = [bc][q][r][d]
    dec32<<<dim3(72, 1, BC), 256, SM_DEC32>>>(bufC, wfHi + 3*1536, wfLo + 3*1536, bufB, 2304);
    // S5: contract q.  bufB[bc][q][rd] (J=6144) -> bufA = [bc][r][d][h]
    dec64<<<dim3(96, 1, BC), 256, SM_DEC64>>>(bufB, wfHi + 4*1536, wfLo + 4*1536, bufA, 6144);
    // S6: contract r.  bufA[bc][r][dh] (J=16384) -> out = [b][c][d][h][w]
    dec64<<<dim3(256, 1, BC), 256, SM_DEC64>>>(bufA, wfHi + 5*1536, wfLo + 5*1536, out, 16384);
}